// round 1
// baseline (speedup 1.0000x reference)
#include <cuda_runtime.h>

// ConvolutionalCapsule EM-routing, fully fused: one CTA per output spatial
// position. Votes [144][16][16] f32 live in shared memory (never touch HBM).
//
// Shapes (fixed): B=8, H=W=14, K=3, stride 1 -> oh=ow=12, N=1152 positions.
// I = 9*16 = 144 input capsules/position, O = 16 output caps, P = 16 pose elems.
// 3 EM iterations, inv_temp = 1,2,3.

#define BATCH   8
#define HW      14
#define OHW     12
#define NPOS    (BATCH * OHW * OHW)   // 1152
#define NI      144
#define NO      16
#define ICH     16
#define VSTRIDE 260                   // words per i in votes (multiple of 4, !=256 mod 32 games not needed: reads use i*260+tid -> conflict-free)
#define CAP_EPS 1e-9f

// Shared memory layout (floats):
//   votes   [144*260]  = 37440
//   pose_sh [2304]
//   rr_sm   [144*17]   = 2448
//   z_sm    [144*17]   = 2448
//   a_sh    [144]
//   zc_sm   [16]
// total = 44800 floats = 179200 B  (+ pad) < 227 KB
#define SMEM_FLOATS (NI*VSTRIDE + 2304 + 2448 + 2448 + 144 + 16)
#define SMEM_BYTES  (SMEM_FLOATS * 4)

__global__ __launch_bounds__(256, 1)
void capsule_em_kernel(const float* __restrict__ g_pose,
                       const float* __restrict__ g_act,
                       const float* __restrict__ g_w,
                       const float* __restrict__ g_bv,
                       const float* __restrict__ g_ba,
                       float* __restrict__ out)
{
    extern __shared__ float sm[];
    float* votes   = sm;                        // [i*VSTRIDE + o*16 + p]
    float* pose_sh = votes + NI * VSTRIDE;      // [i*16 + e]
    float* rr_sm   = pose_sh + 2304;            // [i*17 + o]
    float* z_sm    = rr_sm + 2448;              // [i*17 + o]
    float* a_sh    = z_sm + 2448;               // [i]
    float* zc_sm   = a_sh + NI;                 // [o]

    const int tid = threadIdx.x;
    const int n   = blockIdx.x;
    const int b   = n / (OHW * OHW);
    const int rem = n - b * (OHW * OHW);
    const int h0  = rem / OHW;
    const int w0  = rem - h0 * OHW;

    // ---- Stage pose tile (9 patches x 256 ch, float4) + activations + rr init ----
    {
        const float4* gp4 = (const float4*)g_pose;
        float4* ps4 = (float4*)pose_sh;
        #pragma unroll
        for (int idx = tid; idx < 576; idx += 256) {
            int kk = idx >> 6;                  // patch 0..8
            int c4 = idx & 63;                  // float4 within 256 channels
            int di = kk / 3, dj = kk - di * 3;
            int pix = (b * HW + h0 + di) * HW + (w0 + dj);
            ps4[idx] = gp4[pix * 64 + c4];
        }
        if (tid < NI) {
            int kk = tid >> 4;
            int cap = tid & 15;
            int di = kk / 3, dj = kk - di * 3;
            int pix = (b * HW + h0 + di) * HW + (w0 + dj);
            a_sh[tid] = g_act[pix * ICH + cap];
        }
        for (int idx = tid; idx < NI * 17; idx += 256)
            rr_sm[idx] = 1.0f / 16.0f;
    }
    __syncthreads();

    // ---- Compute votes: votes[i][o][x][z] = sum_y pose[i][x][y] * w[i][o][y][z] ----
    {
        const int vo = tid & 15;        // output capsule
        const int c  = tid >> 4;        // i = c + 16*j
        const float4* w4 = (const float4*)g_w;      // w[i][o][y][z] -> w4[i*64 + o*4 + y]
        const float4* p4 = (const float4*)pose_sh;  // pose row x -> p4[i*4 + x]
        #pragma unroll
        for (int j = 0; j < 9; j++) {
            int i = c + 16 * j;
            float4 pr0 = p4[i * 4 + 0];
            float4 pr1 = p4[i * 4 + 1];
            float4 pr2 = p4[i * 4 + 2];
            float4 pr3 = p4[i * 4 + 3];
            float4 wr0 = w4[i * 64 + vo * 4 + 0];
            float4 wr1 = w4[i * 64 + vo * 4 + 1];
            float4 wr2 = w4[i * 64 + vo * 4 + 2];
            float4 wr3 = w4[i * 64 + vo * 4 + 3];
            float4* vout = (float4*)(votes + i * VSTRIDE + vo * 16);
            #define VROW(PR, X) { float4 r;                                   \
                r.x = PR.x*wr0.x + PR.y*wr1.x + PR.z*wr2.x + PR.w*wr3.x;      \
                r.y = PR.x*wr0.y + PR.y*wr1.y + PR.z*wr2.y + PR.w*wr3.y;      \
                r.z = PR.x*wr0.z + PR.y*wr1.z + PR.z*wr2.z + PR.w*wr3.z;      \
                r.w = PR.x*wr0.w + PR.y*wr1.w + PR.z*wr2.w + PR.w*wr3.w;      \
                vout[X] = r; }
            VROW(pr0, 0)
            VROW(pr1, 1)
            VROW(pr2, 2)
            VROW(pr3, 3)
            #undef VROW
        }
    }
    __syncthreads();

    // ---- EM routing: thread = (o, p), o = tid>>4, p = tid&15 ----
    const int o = tid >> 4;
    const int p = tid & 15;
    const float bvo = g_bv[o];
    const float bao = g_ba[o];
    float mean = 0.0f, act = 0.0f;

    #pragma unroll 1
    for (int t = 0; t < 3; t++) {
        const float inv_temp = 1.0f + (float)t;

        // M-step: one-pass weighted moments over i for this (o,p)
        float S0 = 0.0f, S1 = 0.0f, S2 = 0.0f;
        #pragma unroll 4
        for (int i = 0; i < NI; i++) {
            float rp = rr_sm[i * 17 + o] * a_sh[i];   // broadcast LDS
            float v  = votes[i * VSTRIDE + tid];      // conflict-free LDS
            S0 += rp;
            S1 += rp * v;
            S2 += rp * v * v;
        }
        mean = S1 / S0;
        float var  = fmaxf(S2 / S0 - mean * mean, 0.0f);
        float stdv = sqrtf(var);
        float lstd = __logf(stdv + CAP_EPS);

        // L = sum over p of log(std+eps)  (16-lane butterfly)
        float L = lstd;
        #pragma unroll
        for (int m = 8; m; m >>= 1) L += __shfl_xor_sync(0xffffffffu, L, m);

        float cost = S0 * (16.0f * bvo + L);
        act = 1.0f / (1.0f + __expf(-inv_temp * (bao - cost)));

        if (t < 2) {
            // E-step
            float inv2var = 1.0f / (2.0f * var + CAP_EPS);
            if (p == 0) zc_sm[o] = __logf(act + CAP_EPS) - L;
            __syncthreads();
            float zc = zc_sm[o];

            #pragma unroll 2
            for (int i = 0; i < NI; i++) {
                float v = votes[i * VSTRIDE + tid];
                float d = v - mean;
                float s = d * d * inv2var;
                #pragma unroll
                for (int m = 8; m; m >>= 1) s += __shfl_xor_sync(0xffffffffu, s, m);
                if (p == 0) z_sm[i * 17 + o] = zc - s;
            }
            __syncthreads();

            // softmax over o per input capsule i (rows padded to 17: conflict-free)
            if (tid < NI) {
                float zr[16];
                float zmax = -1e30f;
                #pragma unroll
                for (int oo = 0; oo < 16; oo++) {
                    zr[oo] = z_sm[tid * 17 + oo];
                    zmax = fmaxf(zmax, zr[oo]);
                }
                float se = 0.0f;
                #pragma unroll
                for (int oo = 0; oo < 16; oo++) {
                    zr[oo] = __expf(zr[oo] - zmax);
                    se += zr[oo];
                }
                float inv = 1.0f / se;
                #pragma unroll
                for (int oo = 0; oo < 16; oo++)
                    rr_sm[tid * 17 + oo] = zr[oo] * inv;
            }
            __syncthreads();
        }
    }

    // ---- Outputs: pose [N,16,4,4] then activation [N,16], concatenated ----
    out[n * 256 + tid] = mean;                       // tid = o*16 + p matches [o][x][z]
    if (p == 0) out[NPOS * 256 + n * 16 + o] = act;
}

extern "C" void kernel_launch(void* const* d_in, const int* in_sizes, int n_in,
                              void* d_out, int out_size)
{
    const float* g_pose = (const float*)d_in[0];
    const float* g_act  = (const float*)d_in[1];
    const float* g_w    = (const float*)d_in[2];
    const float* g_bv   = (const float*)d_in[3];
    const float* g_ba   = (const float*)d_in[4];
    float* out = (float*)d_out;

    cudaFuncSetAttribute(capsule_em_kernel,
                         cudaFuncAttributeMaxDynamicSharedMemorySize, SMEM_BYTES);
    capsule_em_kernel<<<NPOS, 256, SMEM_BYTES>>>(g_pose, g_act, g_w, g_bv, g_ba, out);
}

// round 2
// speedup vs baseline: 2.8206x; 2.8206x over previous
#include <cuda_runtime.h>

// ConvolutionalCapsule EM-routing, fully fused, one CTA per output position.
// Votes stored TRANSPOSED in SMEM: votes_t[(o*16+p)*148 + 16*o + i]
//  - M-step: thread (o,p) reads float4 across i (conflict-free, 20l banks)
//  - E-step: thread (o,i_lo) reads 16 scalars across p (disjoint bank halves
//    for the two o-groups in a warp thanks to the +16*o skew)
// No dependent shuffle chains; 2 barriers per EM iteration.

#define BATCH   8
#define HW      14
#define OHW     12
#define NPOS    (BATCH * OHW * OHW)   // 1152
#define NI      144
#define VSTR    148                   // words per (o,p) row in votes_t
#define RSTR    152                   // words per o in rr' (rp)
#define CAP_EPS 1e-9f

#define VROWOFF(o, p) (((o)*16 + (p)) * VSTR + 16 * (o))

// SMEM layout (floats)
#define OFF_POSE 38144                // votes_t occupies [0, 38124)
#define OFF_RP   (OFF_POSE + 144*20)  // pose padded: 20 words per capsule
#define OFF_Z    (OFF_RP + 16*RSTR)
#define OFF_A    (OFF_Z + NI*17)
#define SMEM_FLOATS (OFF_A + NI)
#define SMEM_BYTES  (SMEM_FLOATS * 4) // 184192 B < 227 KB

__global__ __launch_bounds__(256, 1)
void capsule_em_kernel(const float* __restrict__ g_pose,
                       const float* __restrict__ g_act,
                       const float* __restrict__ g_w,
                       const float* __restrict__ g_bv,
                       const float* __restrict__ g_ba,
                       float* __restrict__ out)
{
    extern __shared__ float sm[];
    float* votes_t = sm;
    float* pose_sh = sm + OFF_POSE;   // [i*20 + 4*x + y] (float4 stride 5)
    float* rp_sm   = sm + OFF_RP;     // rr' = rr * a, layout [o*152 + i]
    float* z_sm    = sm + OFF_Z;      // [i*17 + o]
    float* a_sh    = sm + OFF_A;      // [i]

    const int tid = threadIdx.x;
    const int n   = blockIdx.x;
    const int b   = n / (OHW * OHW);
    const int rem = n - b * (OHW * OHW);
    const int h0  = rem / OHW;
    const int w0  = rem - h0 * OHW;

    const int o = tid >> 4;   // output capsule (all phases)
    const int p = tid & 15;   // pose elem (M) / i_lo (E) / i_lo (vote compute)

    // ---- Stage pose tile + activations ----
    {
        const float4* gp4 = (const float4*)g_pose;
        float4* ps4 = (float4*)pose_sh;   // stride 5 float4s per capsule
        #pragma unroll
        for (int idx = tid; idx < 576; idx += 256) {
            int kk = idx >> 6;            // patch 0..8
            int c4 = idx & 63;            // cap*4 + x
            int di = kk / 3, dj = kk - di * 3;
            int pix = (b * HW + h0 + di) * HW + (w0 + dj);
            int cap = c4 >> 2, x = c4 & 3;
            ps4[(kk * 16 + cap) * 5 + x] = gp4[pix * 64 + c4];
        }
        if (tid < NI) {
            int kk = tid >> 4;
            int cap = tid & 15;
            int di = kk / 3, dj = kk - di * 3;
            int pix = (b * HW + h0 + di) * HW + (w0 + dj);
            a_sh[tid] = g_act[pix * 16 + cap];
        }
    }
    __syncthreads();

    // ---- Votes + rr' init.  votes[i][o][x][z] = sum_y pose[i][x][y]*w[i][o][y][z]
    {
        const float4* w4 = (const float4*)g_w;       // [i*64 + o*4 + y]
        const float4* p4 = (const float4*)pose_sh;   // [i*5 + x]
        #pragma unroll
        for (int j = 0; j < 9; j++) {
            int i = p + 16 * j;
            float4 pr0 = p4[i * 5 + 0];
            float4 pr1 = p4[i * 5 + 1];
            float4 pr2 = p4[i * 5 + 2];
            float4 pr3 = p4[i * 5 + 3];
            float4 wr0 = w4[i * 64 + o * 4 + 0];
            float4 wr1 = w4[i * 64 + o * 4 + 1];
            float4 wr2 = w4[i * 64 + o * 4 + 2];
            float4 wr3 = w4[i * 64 + o * 4 + 3];
            float* vdst = votes_t + VROWOFF(o, 0) + i;
            #define VROW(PR, X) {                                              \
                vdst[(4*(X)+0)*VSTR] = PR.x*wr0.x + PR.y*wr1.x + PR.z*wr2.x + PR.w*wr3.x; \
                vdst[(4*(X)+1)*VSTR] = PR.x*wr0.y + PR.y*wr1.y + PR.z*wr2.y + PR.w*wr3.y; \
                vdst[(4*(X)+2)*VSTR] = PR.x*wr0.z + PR.y*wr1.z + PR.z*wr2.z + PR.w*wr3.z; \
                vdst[(4*(X)+3)*VSTR] = PR.x*wr0.w + PR.y*wr1.w + PR.z*wr2.w + PR.w*wr3.w; }
            VROW(pr0, 0)
            VROW(pr1, 1)
            VROW(pr2, 2)
            VROW(pr3, 3)
            #undef VROW
            rp_sm[o * RSTR + i] = a_sh[i] * 0.0625f;   // rr(1/16) * a
        }
    }
    __syncthreads();

    // ---- EM routing ----
    const float bvo = g_bv[o];
    const float bao = g_ba[o];
    float mean = 0.0f, act = 0.0f;

    #pragma unroll 1
    for (int t = 0; t < 3; t++) {
        const float inv_temp = 1.0f + (float)t;

        // M-step: float4 sweep across i for this (o,p)
        float4 A0 = {0,0,0,0}, A1 = {0,0,0,0}, A2 = {0,0,0,0};
        {
            const float4* vr = (const float4*)(votes_t + VROWOFF(o, p));
            const float4* rr = (const float4*)(rp_sm + o * RSTR);
            #pragma unroll
            for (int r = 0; r < 36; r++) {
                float4 v = vr[r];
                float4 q = rr[r];
                A0.x += q.x;         A0.y += q.y;         A0.z += q.z;         A0.w += q.w;
                A1.x = fmaf(q.x, v.x, A1.x); A1.y = fmaf(q.y, v.y, A1.y);
                A1.z = fmaf(q.z, v.z, A1.z); A1.w = fmaf(q.w, v.w, A1.w);
                float qx = q.x * v.x, qy = q.y * v.y, qz = q.z * v.z, qw = q.w * v.w;
                A2.x = fmaf(qx, v.x, A2.x); A2.y = fmaf(qy, v.y, A2.y);
                A2.z = fmaf(qz, v.z, A2.z); A2.w = fmaf(qw, v.w, A2.w);
            }
        }
        float S0 = (A0.x + A0.y) + (A0.z + A0.w);
        float S1 = (A1.x + A1.y) + (A1.z + A1.w);
        float S2 = (A2.x + A2.y) + (A2.z + A2.w);

        float invS0 = __fdividef(1.0f, S0);
        mean = S1 * invS0;
        float var  = fmaxf(S2 * invS0 - mean * mean, 0.0f);
        float stdv = sqrtf(var);
        float lstd = __logf(stdv + CAP_EPS);

        // L = sum_p log(std+eps): 16-lane butterfly (only reduction chain left)
        float L = lstd;
        #pragma unroll
        for (int m = 8; m; m >>= 1) L += __shfl_xor_sync(0xffffffffu, L, m);

        float cost = S0 * (16.0f * bvo + L);
        act = 1.0f / (1.0f + __expf(-inv_temp * (bao - cost)));

        if (t < 2) {
            // E-step: thread handles (o, i_lo=p), 9 i values, reduce over pp.
            float iv = __fdividef(1.0f, 2.0f * var + CAP_EPS);
            float zc = __logf(act + CAP_EPS) - L;

            // gather mean/iv of all 16 p-lanes for my o (independent shuffles)
            float mr[16], ir[16];
            const unsigned half = (unsigned)(tid & 16);
            #pragma unroll
            for (int pp = 0; pp < 16; pp++) {
                mr[pp] = __shfl_sync(0xffffffffu, mean, half | pp);
                ir[pp] = __shfl_sync(0xffffffffu, iv,   half | pp);
            }

            const float* vbase = votes_t + VROWOFF(o, 0) + p;
            #pragma unroll
            for (int r = 0; r < 9; r++) {
                int ioff = 16 * r;
                float s = 0.0f;
                #pragma unroll
                for (int pp = 0; pp < 16; pp++) {
                    float v = vbase[pp * VSTR + ioff];
                    float d = v - mr[pp];
                    s = fmaf(d * ir[pp], d, s);
                }
                z_sm[(p + ioff) * 17 + o] = zc - s;
            }
            __syncthreads();

            // softmax over o per input capsule i; fold a into rr'
            if (tid < NI) {
                float zr[16];
                float zmax = -1e30f;
                #pragma unroll
                for (int oo = 0; oo < 16; oo++) {
                    zr[oo] = z_sm[tid * 17 + oo];
                    zmax = fmaxf(zmax, zr[oo]);
                }
                float se = 0.0f;
                #pragma unroll
                for (int oo = 0; oo < 16; oo++) {
                    zr[oo] = __expf(zr[oo] - zmax);
                    se += zr[oo];
                }
                float scale = __fdividef(a_sh[tid], se);
                #pragma unroll
                for (int oo = 0; oo < 16; oo++)
                    rp_sm[oo * RSTR + tid] = zr[oo] * scale;
            }
            __syncthreads();
        }
    }

    // ---- Outputs: pose [N,16,4,4] then activation [N,16] ----
    out[n * 256 + tid] = mean;
    if (p == 0) out[NPOS * 256 + n * 16 + o] = act;
}

extern "C" void kernel_launch(void* const* d_in, const int* in_sizes, int n_in,
                              void* d_out, int out_size)
{
    const float* g_pose = (const float*)d_in[0];
    const float* g_act  = (const float*)d_in[1];
    const float* g_w    = (const float*)d_in[2];
    const float* g_bv   = (const float*)d_in[3];
    const float* g_ba   = (const float*)d_in[4];
    float* out = (float*)d_out;

    cudaFuncSetAttribute(capsule_em_kernel,
                         cudaFuncAttributeMaxDynamicSharedMemorySize, SMEM_BYTES);
    capsule_em_kernel<<<NPOS, 256, SMEM_BYTES>>>(g_pose, g_act, g_w, g_bv, g_ba, out);
}

// round 5
// speedup vs baseline: 2.9234x; 1.0364x over previous
#include <cuda_runtime.h>

// ConvolutionalCapsule EM-routing, fully fused, one CTA per output position.
// All-f32 (precision-safe). Votes transposed in SMEM:
//   votes_t[(o*16+p)*148 + 16*o + i]
// NEW vs R2: M-step keeps its 144 votes in registers (float4 vreg[36]).
// M-step 0 loads+stashes; M-steps 1,2 read no vote data from SMEM at all.
// Math is bit-identical to the R2 kernel.

#define BATCH   8
#define HW      14
#define OHW     12
#define NPOS    (BATCH * OHW * OHW)   // 1152
#define NI      144
#define VSTR    148                   // words per (o,p) row in votes_t
#define RSTR    152                   // words per o in rr' (rp)
#define CAP_EPS 1e-9f

#define VROWOFF(o, p) (((o)*16 + (p)) * VSTR + 16 * (o))

// SMEM layout (floats)
#define OFF_POSE 38144                // votes_t occupies [0, 38124)
#define OFF_RP   (OFF_POSE + 144*20)  // pose padded: 20 words per capsule
#define OFF_Z    (OFF_RP + 16*RSTR)
#define OFF_A    (OFF_Z + NI*17)
#define SMEM_FLOATS (OFF_A + NI)
#define SMEM_BYTES  (SMEM_FLOATS * 4) // 184192 B < 227 KB, 1 CTA/SM

__global__ __launch_bounds__(256, 1)
void capsule_em_kernel(const float* __restrict__ g_pose,
                       const float* __restrict__ g_act,
                       const float* __restrict__ g_w,
                       const float* __restrict__ g_bv,
                       const float* __restrict__ g_ba,
                       float* __restrict__ out)
{
    extern __shared__ float sm[];
    float* votes_t = sm;
    float* pose_sh = sm + OFF_POSE;   // [i*20 + 4*x + y] (float4 stride 5)
    float* rp_sm   = sm + OFF_RP;     // rr' = rr * a, layout [o*152 + i]
    float* z_sm    = sm + OFF_Z;      // [i*17 + o]
    float* a_sh    = sm + OFF_A;      // [i]

    const int tid = threadIdx.x;
    const int n   = blockIdx.x;
    const int b   = n / (OHW * OHW);
    const int rem = n - b * (OHW * OHW);
    const int h0  = rem / OHW;
    const int w0  = rem - h0 * OHW;

    const int o = tid >> 4;   // output capsule
    const int p = tid & 15;   // pose elem (M) / i_lo (E, vote compute)

    // ---- Stage pose tile + activations ----
    {
        const float4* gp4 = (const float4*)g_pose;
        float4* ps4 = (float4*)pose_sh;
        #pragma unroll
        for (int idx = tid; idx < 576; idx += 256) {
            int kk = idx >> 6;            // patch 0..8
            int c4 = idx & 63;            // cap*4 + x
            int di = kk / 3, dj = kk - di * 3;
            int pix = (b * HW + h0 + di) * HW + (w0 + dj);
            int cap = c4 >> 2, x = c4 & 3;
            ps4[(kk * 16 + cap) * 5 + x] = gp4[pix * 64 + c4];
        }
        if (tid < NI) {
            int kk = tid >> 4;
            int cap = tid & 15;
            int di = kk / 3, dj = kk - di * 3;
            int pix = (b * HW + h0 + di) * HW + (w0 + dj);
            a_sh[tid] = g_act[pix * 16 + cap];
        }
    }
    __syncthreads();

    // ---- Votes + rr' init.  votes[i][o][x][z] = sum_y pose[i][x][y]*w[i][o][y][z]
    {
        const float4* w4 = (const float4*)g_w;       // [i*64 + o*4 + y]
        const float4* p4 = (const float4*)pose_sh;   // [i*5 + x]
        #pragma unroll
        for (int j = 0; j < 9; j++) {
            int i = p + 16 * j;
            float4 pr0 = p4[i * 5 + 0];
            float4 pr1 = p4[i * 5 + 1];
            float4 pr2 = p4[i * 5 + 2];
            float4 pr3 = p4[i * 5 + 3];
            float4 wr0 = w4[i * 64 + o * 4 + 0];
            float4 wr1 = w4[i * 64 + o * 4 + 1];
            float4 wr2 = w4[i * 64 + o * 4 + 2];
            float4 wr3 = w4[i * 64 + o * 4 + 3];
            float* vdst = votes_t + VROWOFF(o, 0) + i;
            #define VROW(PR, X) {                                              \
                vdst[(4*(X)+0)*VSTR] = PR.x*wr0.x + PR.y*wr1.x + PR.z*wr2.x + PR.w*wr3.x; \
                vdst[(4*(X)+1)*VSTR] = PR.x*wr0.y + PR.y*wr1.y + PR.z*wr2.y + PR.w*wr3.y; \
                vdst[(4*(X)+2)*VSTR] = PR.x*wr0.z + PR.y*wr1.z + PR.z*wr2.z + PR.w*wr3.z; \
                vdst[(4*(X)+3)*VSTR] = PR.x*wr0.w + PR.y*wr1.w + PR.z*wr2.w + PR.w*wr3.w; }
            VROW(pr0, 0)
            VROW(pr1, 1)
            VROW(pr2, 2)
            VROW(pr3, 3)
            #undef VROW
            rp_sm[o * RSTR + i] = a_sh[i] * 0.0625f;   // rr(1/16) * a
        }
    }
    __syncthreads();

    // ---- EM routing ----
    const float bvo = g_bv[o];
    const float bao = g_ba[o];
    float mean = 0.0f, act = 0.0f;

    float4 vreg[36];   // this thread's 144 votes, register-resident after t=0

    #define MACC(V, Q) {                                                   \
        A0.x += Q.x;                 A0.y += Q.y;                          \
        A0.z += Q.z;                 A0.w += Q.w;                          \
        A1.x = fmaf(Q.x, V.x, A1.x); A1.y = fmaf(Q.y, V.y, A1.y);          \
        A1.z = fmaf(Q.z, V.z, A1.z); A1.w = fmaf(Q.w, V.w, A1.w);          \
        A2.x = fmaf(Q.x * V.x, V.x, A2.x); A2.y = fmaf(Q.y * V.y, V.y, A2.y); \
        A2.z = fmaf(Q.z * V.z, V.z, A2.z); A2.w = fmaf(Q.w * V.w, V.w, A2.w); }

    #pragma unroll 1
    for (int t = 0; t < 3; t++) {
        const float inv_temp = 1.0f + (float)t;

        // M-step: weighted moments over i for this (o,p)
        float4 A0 = {0,0,0,0}, A1 = {0,0,0,0}, A2 = {0,0,0,0};
        {
            const float4* rr = (const float4*)(rp_sm + o * RSTR);  // broadcast
            if (t == 0) {
                const float4* vr = (const float4*)(votes_t + VROWOFF(o, p));
                #pragma unroll
                for (int r = 0; r < 36; r++) {
                    float4 v = vr[r];
                    vreg[r] = v;                 // stash for t=1,2
                    float4 q = rr[r];
                    MACC(v, q)
                }
            } else {
                #pragma unroll
                for (int r = 0; r < 36; r++) {
                    float4 v = vreg[r];          // register-resident
                    float4 q = rr[r];
                    MACC(v, q)
                }
            }
        }
        float S0 = (A0.x + A0.y) + (A0.z + A0.w);
        float S1 = (A1.x + A1.y) + (A1.z + A1.w);
        float S2 = (A2.x + A2.y) + (A2.z + A2.w);

        float invS0 = __fdividef(1.0f, S0);
        mean = S1 * invS0;
        float var  = fmaxf(S2 * invS0 - mean * mean, 0.0f);
        float stdv = sqrtf(var);
        float lstd = __logf(stdv + CAP_EPS);

        // L = sum_p log(std+eps): 16-lane butterfly
        float L = lstd;
        #pragma unroll
        for (int m = 8; m; m >>= 1) L += __shfl_xor_sync(0xffffffffu, L, m);

        float cost = S0 * (16.0f * bvo + L);
        act = 1.0f / (1.0f + __expf(-inv_temp * (bao - cost)));

        if (t < 2) {
            // E-step: thread handles (o, i_lo=p), 9 i values, reduce over pp.
            float iv = __fdividef(1.0f, 2.0f * var + CAP_EPS);
            float zc = __logf(act + CAP_EPS) - L;

            // gather mean/iv of all 16 p-lanes for my o (independent shuffles)
            float mr[16], ir[16];
            const unsigned half_sel = (unsigned)(tid & 16);
            #pragma unroll
            for (int pp = 0; pp < 16; pp++) {
                mr[pp] = __shfl_sync(0xffffffffu, mean, half_sel | pp);
                ir[pp] = __shfl_sync(0xffffffffu, iv,   half_sel | pp);
            }

            const float* vbase = votes_t + VROWOFF(o, 0) + p;
            #pragma unroll
            for (int r = 0; r < 9; r++) {
                int ioff = 16 * r;
                float s = 0.0f;
                #pragma unroll
                for (int pp = 0; pp < 16; pp++) {
                    float v = vbase[pp * VSTR + ioff];
                    float d = v - mr[pp];
                    s = fmaf(d * ir[pp], d, s);
                }
                z_sm[(p + ioff) * 17 + o] = zc - s;
            }
            __syncthreads();

            // softmax over o per input capsule i; fold a into rr'
            if (tid < NI) {
                float zr[16];
                float zmax = -1e30f;
                #pragma unroll
                for (int oo = 0; oo < 16; oo++) {
                    zr[oo] = z_sm[tid * 17 + oo];
                    zmax = fmaxf(zmax, zr[oo]);
                }
                float se = 0.0f;
                #pragma unroll
                for (int oo = 0; oo < 16; oo++) {
                    zr[oo] = __expf(zr[oo] - zmax);
                    se += zr[oo];
                }
                float scale = __fdividef(a_sh[tid], se);
                #pragma unroll
                for (int oo = 0; oo < 16; oo++)
                    rp_sm[oo * RSTR + tid] = zr[oo] * scale;
            }
            __syncthreads();
        }
    }
    #undef MACC

    // ---- Outputs: pose [N,16,4,4] then activation [N,16] ----
    out[n * 256 + tid] = mean;
    if (p == 0) out[NPOS * 256 + n * 16 + o] = act;
}

extern "C" void kernel_launch(void* const* d_in, const int* in_sizes, int n_in,
                              void* d_out, int out_size)
{
    const float* g_pose = (const float*)d_in[0];
    const float* g_act  = (const float*)d_in[1];
    const float* g_w    = (const float*)d_in[2];
    const float* g_bv   = (const float*)d_in[3];
    const float* g_ba   = (const float*)d_in[4];
    float* out = (float*)d_out;

    cudaFuncSetAttribute(capsule_em_kernel,
                         cudaFuncAttributeMaxDynamicSharedMemorySize, SMEM_BYTES);
    capsule_em_kernel<<<NPOS, 256, SMEM_BYTES>>>(g_pose, g_act, g_w, g_bv, g_ba, out);
}